// round 16
// baseline (speedup 1.0000x reference)
#include <cuda_runtime.h>
#include <cuda_fp16.h>
#include <math.h>
#include <cstdint>
#include <cstring>

// Problem constants
#define B_ 2
#define S_ 2048
#define D_ 2048
#define H_ 16
#define DK_ 128

static const size_t NBSD = (size_t)B_ * S_ * D_;
// fp32 planes: Qlin, Klin, Vlin (QKV GEMM output)
__device__ float g_scratch[3 * (size_t)B_ * S_ * D_];
// fp16 planes: Qh, Kh, O16
__device__ __half g_h16[3 * (size_t)B_ * S_ * D_];
// packed+transposed V: u32 half2(V[2s2][d],V[2s2+1][d]) at [b,h][d][s2]
__device__ uint32_t g_vp[(size_t)B_ * S_ * D_ / 2];
__device__ __half g_x16[(size_t)B_ * S_ * D_];        // fp16 x
__device__ __half g_w16[4 * (size_t)D_ * D_];         // fp16 Wq,Wk,Wv,Wo
__device__ float g_bias[3 * D_];                      // concat bq,bk,bv

// ============================================================================
// Helpers
// ============================================================================
__device__ __forceinline__ uint32_t smem_to_u32(const void* smem_ptr) {
    uint32_t addr;
    asm("{ .reg .u64 tmp; cvta.to.shared.u64 tmp, %1; cvt.u32.u64 %0, tmp; }"
        : "=r"(addr) : "l"(smem_ptr));
    return addr;
}

__device__ __forceinline__ uint32_t h2_as_u32(__half2 h) {
    uint32_t u;
    memcpy(&u, &h, 4);
    return u;
}

__device__ __forceinline__ void cp_async16(uint32_t smem_addr, const void* gptr) {
    asm volatile("cp.async.cg.shared.global [%0], [%1], 16;"
                 :: "r"(smem_addr), "l"(gptr));
}
#define CP_ASYNC_COMMIT() asm volatile("cp.async.commit_group;" ::: "memory")
#define CP_ASYNC_WAIT(n)  asm volatile("cp.async.wait_group %0;" :: "n"(n) : "memory")

__device__ __forceinline__ void ldsm_x4(uint32_t* r, uint32_t addr) {
    asm volatile("ldmatrix.sync.aligned.m8n8.x4.shared.b16 {%0,%1,%2,%3}, [%4];"
                 : "=r"(r[0]), "=r"(r[1]), "=r"(r[2]), "=r"(r[3]) : "r"(addr));
}

__device__ __forceinline__ void mma_f16_16n8k16(float* d, const uint32_t* a,
                                                const uint32_t* b) {
    asm volatile(
        "mma.sync.aligned.m16n8k16.row.col.f32.f16.f16.f32 "
        "{%0,%1,%2,%3}, {%4,%5,%6,%7}, {%8,%9}, {%0,%1,%2,%3};"
        : "+f"(d[0]), "+f"(d[1]), "+f"(d[2]), "+f"(d[3])
        : "r"(a[0]), "r"(a[1]), "r"(a[2]), "r"(a[3]), "r"(b[0]), "r"(b[1]));
}

// ============================================================================
// fp16 conversion pre-passes
// ============================================================================
__global__ __launch_bounds__(256) void f32_to_f16_kernel(
    const float* __restrict__ in, __half* __restrict__ out, int n4)
{
    int i = blockIdx.x * 256 + threadIdx.x;
    if (i >= n4) return;
    float4 v = ((const float4*)in)[i];
    uint2 w;
    w.x = h2_as_u32(__floats2half2_rn(v.x, v.y));
    w.y = h2_as_u32(__floats2half2_rn(v.z, v.w));
    ((uint2*)out)[i] = w;
}

__global__ __launch_bounds__(256) void w4_to_f16_kernel(
    const float* __restrict__ W0, const float* __restrict__ W1,
    const float* __restrict__ W2, const float* __restrict__ W3,
    __half* __restrict__ out)
{
    int i = blockIdx.x * 256 + threadIdx.x;     // 0 .. 4*2^20-1
    const int per = (D_ * D_) / 4;
    int p = i >> 20, j = i & (per - 1);
    const float* W = (p == 0) ? W0 : (p == 1) ? W1 : (p == 2) ? W2 : W3;
    float4 v = ((const float4*)W)[j];
    uint2 w;
    w.x = h2_as_u32(__floats2half2_rn(v.x, v.y));
    w.y = h2_as_u32(__floats2half2_rn(v.z, v.w));
    ((uint2*)out)[i] = w;
}

// ============================================================================
// fp16 GEMM: C(fp32) = A(fp16)[M,K] @ W(fp16)[N,K]^T + bias.
// BM=128, BN=256, BK=64, 512 threads = 16 warps (4 M x 4 N), warp tile 32x64.
// 4 warps per SMSP for issue-slot coverage. All fragments via ldmatrix.x4.
// ============================================================================
#define HSTR 72                                  // halves per row (64 + 8 pad)
#define GA_BYTES (128 * HSTR * 2)                // 18432
#define GEMM_STAGE_BYTES ((128 + 256) * HSTR * 2)  // 55296
#define GEMM_SMEM (3 * GEMM_STAGE_BYTES + 16)

__device__ __forceinline__ void gemm16_load_stage(
    const __half* __restrict__ A, const __half* __restrict__ W,
    int row0, int col0, int K, int kc, uint32_t sbase, int tid)
{
#pragma unroll
    for (int i = 0; i < 2; i++) {
        int q = i * 512 + tid;           // 0..1023
        int r = q >> 3, c = q & 7;
        cp_async16(sbase + (uint32_t)(r * 144 + c * 16),
                   A + (size_t)(row0 + r) * K + kc * 64 + c * 8);
    }
#pragma unroll
    for (int i = 0; i < 4; i++) {
        int q = i * 512 + tid;           // 0..2047
        int r = q >> 3, c = q & 7;
        cp_async16(sbase + (uint32_t)GA_BYTES + (uint32_t)(r * 144 + c * 16),
                   W + (size_t)(col0 + r) * K + kc * 64 + c * 8);
    }
    CP_ASYNC_COMMIT();
}

__global__ __launch_bounds__(512) void f16_gemm_nt_bias(
    const __half* __restrict__ A, const __half* __restrict__ W,
    const float* __restrict__ bias, float* __restrict__ C,
    int M, int K, size_t plane_stride)
{
    extern __shared__ __align__(16) char dsm[];

    int tid = threadIdx.x;
    int wid = tid >> 5;
    int lane = tid & 31;
    int gr = lane >> 2;
    int gc = lane & 3;
    int wm = wid & 3;        // 4 m-tiles of 32 rows
    int wn = wid >> 2;       // 4 n-tiles of 64 cols
    int lrow = lane & 7, lsel = lane >> 3;

    int bx = blockIdx.x, by = blockIdx.y;
    int row0 = by * 128, col0 = bx * 256;

    uint32_t sb = smem_to_u32(dsm);
    // A-frag x4: m0=(r,k0) m1=(r+8,k0) m2=(r,k0+8h) m3=(r+8,k0+8h)
    uint32_t afb = (uint32_t)((wm * 32 + (lsel & 1) * 8 + lrow) * 144 +
                              (lsel >> 1) * 16);
    // W-frag x4: m0=(n,k0) m1=(n,k0+8h) m2=(n+8,k0) m3=(n+8,k0+8h)
    uint32_t wfb = (uint32_t)GA_BYTES +
                   (uint32_t)((wn * 64 + (lsel >> 1) * 8 + lrow) * 144 +
                              (lsel & 1) * 16);

    float acc[2][8][4];
#pragma unroll
    for (int i = 0; i < 2; i++)
#pragma unroll
        for (int j = 0; j < 8; j++)
#pragma unroll
            for (int k = 0; k < 4; k++) acc[i][j][k] = 0.f;

    const int NC = K >> 6;   // 32

    gemm16_load_stage(A, W, row0, col0, K, 0, sb + 0 * GEMM_STAGE_BYTES, tid);
    gemm16_load_stage(A, W, row0, col0, K, 1, sb + 1 * GEMM_STAGE_BYTES, tid);

    for (int j = 0; j < NC; j++) {
        if (j + 2 < NC) { CP_ASYNC_WAIT(1); } else { CP_ASYNC_WAIT(0); }
        __syncthreads();

        int jn = j + 2;
        if (jn < NC) {
            gemm16_load_stage(A, W, row0, col0, K, jn,
                              sb + (jn % 3) * GEMM_STAGE_BYTES, tid);
        }

        uint32_t stage_b = sb + (uint32_t)((j % 3) * GEMM_STAGE_BYTES);

#pragma unroll
        for (int kst = 0; kst < 4; kst++) {
            uint32_t af[2][4];
#pragma unroll
            for (int ma = 0; ma < 2; ma++)
                ldsm_x4(af[ma], stage_b + afb +
                        (uint32_t)(ma * 16 * 144) + kst * 32);
            uint32_t wf[4][4];
#pragma unroll
            for (int np = 0; np < 4; np++)
                ldsm_x4(wf[np], stage_b + wfb +
                        (uint32_t)(np * 16 * 144) + kst * 32);
#pragma unroll
            for (int ma = 0; ma < 2; ma++)
#pragma unroll
                for (int np = 0; np < 4; np++) {
                    mma_f16_16n8k16(acc[ma][2 * np], af[ma], &wf[np][0]);
                    mma_f16_16n8k16(acc[ma][2 * np + 1], af[ma], &wf[np][2]);
                }
        }
        __syncthreads();
    }

    // Epilogue: plane routing (col>>11), row stride 2048, fp32 out
    float* Cp = C + (size_t)(col0 >> 11) * plane_stride;
    int colp0 = col0 & 2047;
#pragma unroll
    for (int ma = 0; ma < 2; ma++) {
        int row = row0 + wm * 32 + ma * 16 + gr;
#pragma unroll
        for (int na = 0; na < 8; na++) {
            int colf = col0 + wn * 64 + na * 8 + gc * 2;
            int colp = colp0 + wn * 64 + na * 8 + gc * 2;
            float2 bb = *(const float2*)(bias + colf);
            float2 o0, o1;
            o0.x = acc[ma][na][0] + bb.x;
            o0.y = acc[ma][na][1] + bb.y;
            o1.x = acc[ma][na][2] + bb.x;
            o1.y = acc[ma][na][3] + bb.y;
            *(float2*)(Cp + (size_t)row * D_ + colp) = o0;
            *(float2*)(Cp + (size_t)(row + 8) * D_ + colp) = o1;
        }
    }
}

// ---------------------------------------------------------------------------
// RoPE + relayout. Q, K: fp16 (single plane each).
// ---------------------------------------------------------------------------
__global__ __launch_bounds__(256) void rope_relayout_kernel(
    const float* __restrict__ Qlin, const float* __restrict__ Klin,
    __half* __restrict__ Qh, __half* __restrict__ Kh)
{
    int idx = blockIdx.x * 256 + threadIdx.x;          // B*H*S*64
    if (idx >= B_ * H_ * S_ * 64) return;
    int i  = idx & 63;
    int s  = (idx >> 6) & (S_ - 1);
    int hb = idx >> 17;
    int h  = hb & (H_ - 1);
    int b  = hb >> 4;

    size_t lin = ((size_t)(b * S_ + s)) * D_ + h * DK_ + i;
    size_t out = ((size_t)hb * S_ + s) * DK_ + i;

    float inv = 1.0f / powf(10000.0f, (float)(2 * i) / 128.0f);
    float ang = (float)s * inv;
    float sn, cs;
    sincosf(ang, &sn, &cs);

    float q0 = Qlin[lin], q1 = Qlin[lin + 64];
    Qh[out]      = __float2half_rn(q0 * cs - q1 * sn);
    Qh[out + 64] = __float2half_rn(q1 * cs + q0 * sn);

    float k0 = Klin[lin], k1 = Klin[lin + 64];
    Kh[out]      = __float2half_rn(k0 * cs - k1 * sn);
    Kh[out + 64] = __float2half_rn(k1 * cs + k0 * sn);
}

// ---------------------------------------------------------------------------
// V pack + transpose: [B,S,D] fp32 -> Vt[b,h][d][s2] u32 half2 pairs.
// ---------------------------------------------------------------------------
__global__ __launch_bounds__(256) void v_pack_kernel(
    const float* __restrict__ Vlin, uint32_t* __restrict__ Vp)
{
    __shared__ uint32_t tile[32][33];
    int blk = blockIdx.x;                // B*H * 4 * 32 = 4096
    int s2b = (blk & 31) * 32;
    int db  = ((blk >> 5) & 3) * 32;
    int hb  = blk >> 7;
    int h = hb & (H_ - 1), b = hb >> 4;
    int t = threadIdx.x;

#pragma unroll
    for (int it = 0; it < 4; it++) {
        int idx = it * 256 + t;
        int s2l = idx >> 5, dl = idx & 31;
        const float* src = Vlin +
            ((size_t)(b * S_ + 2 * (s2b + s2l))) * D_ + h * DK_ + db + dl;
        tile[s2l][dl] = h2_as_u32(__floats2half2_rn(src[0], src[D_]));
    }
    __syncthreads();
#pragma unroll
    for (int it = 0; it < 4; it++) {
        int idx = it * 256 + t;
        int dl = idx >> 5, s2l = idx & 31;
        Vp[((size_t)hb * DK_ + db + dl) * (S_ / 2) + s2b + s2l] = tile[s2l][dl];
    }
}

// ---------------------------------------------------------------------------
// Tensor-core flash attention (causal), FA2 + LDSM, single-pass fp16 scores.
// BM=128, BN=64, 8 warps; warp owns 16 q-rows. One barrier per kv-group.
// ---------------------------------------------------------------------------
#define AHSTR 136                        // fp16 K/Q row stride (halves)
#define VTSTR 36                         // Vt row stride (u32)
#define VT_OFF (4352 * 4)                // bytes: Vt tile within stage
#define STG_F 8960                       // stage floats: KH 4352 + VT 4608
#define ATT_FLOATS (3 * STG_F)           // 26880
#define ATT_SMEM (ATT_FLOATS * 4)        // 107520 bytes

__global__ __launch_bounds__(256, 1) void attn_mma_kernel(
    const __half* __restrict__ Qh_g, const __half* __restrict__ Kh_g,
    const uint32_t* __restrict__ Vp_g, __half* __restrict__ O16)
{
    extern __shared__ __align__(16) float sm[];
    uint32_t sb = smem_to_u32(sm);

    int qt = (int)gridDim.x - 1 - (int)blockIdx.x;
    int h = blockIdx.y, b = blockIdx.z;
    int hb = b * H_ + h;
    size_t base = (size_t)hb * S_ * DK_;
    size_t qoff = base + (size_t)qt * 128 * DK_;
    size_t vbase = (size_t)hb * DK_ * (S_ / 2);

    int tid = threadIdx.x;
    int wid = tid >> 5;
    int lane = tid & 31;
    int gr = lane >> 2, gc = lane & 3;

    int r0 = wid * 16 + gr;
    int rbase = qt * 128;

#pragma unroll
    for (int i = 0; i < 8; i++) {
        int q = i * 256 + tid;
        int r = q >> 4, c = q & 15;
        cp_async16(sb + (uint32_t)(r * AHSTR * 2 + c * 16),
                   Qh_g + qoff + (size_t)r * DK_ + c * 8);
    }
    CP_ASYNC_COMMIT();
    CP_ASYNC_WAIT(0);
    __syncthreads();

    uint32_t qh[8][4];
    {
        const __half* Qhp = (const __half*)sm;
#pragma unroll
        for (int kst = 0; kst < 8; kst++) {
            int k0 = kst * 16;
            qh[kst][0] = *(const uint32_t*)&Qhp[r0 * AHSTR + k0 + 2 * gc];
            qh[kst][1] = *(const uint32_t*)&Qhp[(r0 + 8) * AHSTR + k0 + 2 * gc];
            qh[kst][2] = *(const uint32_t*)&Qhp[r0 * AHSTR + k0 + 2 * gc + 8];
            qh[kst][3] = *(const uint32_t*)&Qhp[(r0 + 8) * AHSTR + k0 + 2 * gc + 8];
        }
    }
    __syncthreads();   // stage-0 area free for K/V ring

    int lrow = lane & 7, lsel = lane >> 3;
    uint32_t kfb = (uint32_t)(((lsel >> 1) * 8 + lrow) * (AHSTR * 2) +
                              (lsel & 1) * 16);
    uint32_t vfb = (uint32_t)VT_OFF +
                   (uint32_t)(((lsel >> 1) * 8 + lrow) * (VTSTR * 4)) +
                   (uint32_t)(lsel & 1) * 16u;

    int nkt = 2 * qt + 2;

    auto load_group = [&](int j, int s) {
        size_t kb = base + (size_t)j * 64 * DK_;
        size_t vt = vbase + (size_t)j * 32;
        uint32_t st = sb + (uint32_t)(s * STG_F) * 4;
#pragma unroll
        for (int i = 0; i < 4; i++) {
            int q = i * 256 + tid;   // 0..1023 (64 rows x 16 chunks)
            int r = q >> 4, c = q & 15;
            cp_async16(st + (uint32_t)(r * AHSTR * 2 + c * 16),
                       Kh_g + kb + (size_t)r * DK_ + c * 8);
        }
#pragma unroll
        for (int i = 0; i < 4; i++) {
            int q = i * 256 + tid;   // 0..1023 (128 d-rows x 8 chunks)
            int r = q >> 3, c = q & 7;
            cp_async16(st + VT_OFF + (uint32_t)(r * VTSTR * 4 + c * 16),
                       Vp_g + vt + (size_t)r * (S_ / 2) + c * 4);
        }
        CP_ASYNC_COMMIT();
    };

    load_group(0, 0);
    if (nkt > 1) load_group(1, 1);

    float oacc[16][4];
#pragma unroll
    for (int i = 0; i < 16; i++)
#pragma unroll
        for (int j = 0; j < 4; j++) oacc[i][j] = 0.f;

    float m0 = -1e30f, m1 = -1e30f, l0 = 0.f, l1 = 0.f;
    const float scale = 0.088388347648318440f;

    for (int j = 0; j < nkt; j++) {
        if (j + 1 < nkt) { CP_ASYNC_WAIT(1); } else { CP_ASYNC_WAIT(0); }
        __syncthreads();

        if (j + 2 < nkt) load_group(j + 2, (j + 2) % 3);

        uint32_t stage_b = sb + (uint32_t)((j % 3) * STG_F) * 4;

        // Scores: warp tile 16x64, single-pass fp16 (Qh x Kh)
        float sacc[8][4];
#pragma unroll
        for (int i = 0; i < 8; i++)
#pragma unroll
            for (int k = 0; k < 4; k++) sacc[i][k] = 0.f;

#pragma unroll
        for (int kst = 0; kst < 8; kst++) {
#pragma unroll
            for (int np = 0; np < 4; np++) {
                uint32_t kf[4];
                ldsm_x4(kf, stage_b + kfb +
                        (uint32_t)(np * 16 * AHSTR * 2) + kst * 32);
                mma_f16_16n8k16(sacc[2 * np], qh[kst], &kf[0]);
                mma_f16_16n8k16(sacc[2 * np + 1], qh[kst], &kf[2]);
            }
        }

        // Scale + causal mask (registers only)
        bool diag = (j >= 2 * qt);
        int rg0 = rbase + r0, rg1 = rg0 + 8;
#pragma unroll
        for (int na = 0; na < 8; na++) {
            float s0 = sacc[na][0] * scale;
            float s1 = sacc[na][1] * scale;
            float s2 = sacc[na][2] * scale;
            float s3 = sacc[na][3] * scale;
            if (diag) {
                int cg = j * 64 + na * 8 + 2 * gc;
                if (cg > rg0) s0 = -1e30f;
                if (cg + 1 > rg0) s1 = -1e30f;
                if (cg > rg1) s2 = -1e30f;
                if (cg + 1 > rg1) s3 = -1e30f;
            }
            sacc[na][0] = s0; sacc[na][1] = s1;
            sacc[na][2] = s2; sacc[na][3] = s3;
        }

        // Warp-local online softmax
        float rm0 = -1e30f, rm1 = -1e30f;
#pragma unroll
        for (int na = 0; na < 8; na++) {
            rm0 = fmaxf(rm0, fmaxf(sacc[na][0], sacc[na][1]));
            rm1 = fmaxf(rm1, fmaxf(sacc[na][2], sacc[na][3]));
        }
        rm0 = fmaxf(rm0, __shfl_xor_sync(0xffffffffu, rm0, 1));
        rm0 = fmaxf(rm0, __shfl_xor_sync(0xffffffffu, rm0, 2));
        rm1 = fmaxf(rm1, __shfl_xor_sync(0xffffffffu, rm1, 1));
        rm1 = fmaxf(rm1, __shfl_xor_sync(0xffffffffu, rm1, 2));

        float mn0 = fmaxf(m0, rm0), mn1 = fmaxf(m1, rm1);
        float a0 = __expf(m0 - mn0), a1 = __expf(m1 - mn1);
        m0 = mn0; m1 = mn1;

        uint32_t ap[4][4];
        float sum0 = 0.f, sum1 = 0.f;
#pragma unroll
        for (int kst = 0; kst < 4; kst++) {
            int e = 2 * kst, o = 2 * kst + 1;
            __half2 h00 = __floats2half2_rn(__expf(sacc[e][0] - mn0),
                                            __expf(sacc[e][1] - mn0));
            __half2 h01 = __floats2half2_rn(__expf(sacc[e][2] - mn1),
                                            __expf(sacc[e][3] - mn1));
            __half2 h10 = __floats2half2_rn(__expf(sacc[o][0] - mn0),
                                            __expf(sacc[o][1] - mn0));
            __half2 h11 = __floats2half2_rn(__expf(sacc[o][2] - mn1),
                                            __expf(sacc[o][3] - mn1));
            ap[kst][0] = h2_as_u32(h00);
            ap[kst][1] = h2_as_u32(h01);
            ap[kst][2] = h2_as_u32(h10);
            ap[kst][3] = h2_as_u32(h11);
            float2 f;
            f = __half22float2(h00); sum0 += f.x + f.y;
            f = __half22float2(h10); sum0 += f.x + f.y;
            f = __half22float2(h01); sum1 += f.x + f.y;
            f = __half22float2(h11); sum1 += f.x + f.y;
        }
        sum0 += __shfl_xor_sync(0xffffffffu, sum0, 1);
        sum0 += __shfl_xor_sync(0xffffffffu, sum0, 2);
        sum1 += __shfl_xor_sync(0xffffffffu, sum1, 1);
        sum1 += __shfl_xor_sync(0xffffffffu, sum1, 2);
        l0 = l0 * a0 + sum0;
        l1 = l1 * a1 + sum1;

#pragma unroll
        for (int na = 0; na < 16; na++) {
            oacc[na][0] *= a0; oacc[na][1] *= a0;
            oacc[na][2] *= a1; oacc[na][3] *= a1;
        }

        // PV: warp tile 16x128, V fragments via LDSM
#pragma unroll
        for (int kst = 0; kst < 4; kst++) {
#pragma unroll
            for (int np = 0; np < 8; np++) {
                uint32_t vf[4];
                ldsm_x4(vf, stage_b + vfb +
                        (uint32_t)(np * 16 * VTSTR * 4) + kst * 32);
                mma_f16_16n8k16(oacc[2 * np], ap[kst], vf);
                mma_f16_16n8k16(oacc[2 * np + 1], ap[kst], vf + 2);
            }
        }
    }

    // Epilogue: normalize, write fp16 directly into O16 [B,S,D]
    float li0 = 1.0f / l0;
    float li1 = 1.0f / l1;
    int srow0 = rbase + r0;
    __half* Og0 = O16 + ((size_t)b * S_ + srow0) * D_ + h * DK_;
    __half* Og1 = O16 + ((size_t)b * S_ + srow0 + 8) * D_ + h * DK_;
#pragma unroll
    for (int na = 0; na < 16; na++) {
        int col = na * 8 + 2 * gc;
        *(uint32_t*)(Og0 + col) =
            h2_as_u32(__floats2half2_rn(oacc[na][0] * li0, oacc[na][1] * li0));
        *(uint32_t*)(Og1 + col) =
            h2_as_u32(__floats2half2_rn(oacc[na][2] * li1, oacc[na][3] * li1));
    }
}

// ---------------------------------------------------------------------------
extern "C" void kernel_launch(void* const* d_in, const int* in_sizes, int n_in,
                              void* d_out, int out_size)
{
    const float* x  = (const float*)d_in[0];
    const float* Wq = (const float*)d_in[2];
    const float* bq = (const float*)d_in[3];
    const float* Wk = (const float*)d_in[4];
    const float* bk = (const float*)d_in[5];
    const float* Wv = (const float*)d_in[6];
    const float* bv = (const float*)d_in[7];
    const float* Wo = (const float*)d_in[8];
    const float* bo = (const float*)d_in[9];
    float* out = (float*)d_out;

    float* base = nullptr;
    cudaGetSymbolAddress((void**)&base, g_scratch);
    __half* hbase = nullptr;
    cudaGetSymbolAddress((void**)&hbase, g_h16);
    uint32_t* vp = nullptr;
    cudaGetSymbolAddress((void**)&vp, g_vp);
    __half* x16 = nullptr;
    cudaGetSymbolAddress((void**)&x16, g_x16);
    __half* w16 = nullptr;
    cudaGetSymbolAddress((void**)&w16, g_w16);
    float* biasqkv = nullptr;
    cudaGetSymbolAddress((void**)&biasqkv, g_bias);

    float* Qlin = base;
    float* Klin = base + NBSD;
    float* Vlin = base + 2 * NBSD;
    __half* Qh16 = hbase;
    __half* Kh16 = hbase + NBSD;
    __half* O16  = hbase + 2 * NBSD;
    __half* Wot16 = w16 + 3 * (size_t)D_ * D_;

    const int M = B_ * S_, K = D_;

    cudaMemcpyAsync(biasqkv,          bq, D_ * 4, cudaMemcpyDeviceToDevice);
    cudaMemcpyAsync(biasqkv + D_,     bk, D_ * 4, cudaMemcpyDeviceToDevice);
    cudaMemcpyAsync(biasqkv + 2 * D_, bv, D_ * 4, cudaMemcpyDeviceToDevice);

    {
        int nx4 = (int)(NBSD / 4);
        f32_to_f16_kernel<<<(nx4 + 255) / 256, 256>>>(x, x16, nx4);
        w4_to_f16_kernel<<<16384, 256>>>(Wq, Wk, Wv, Wo, w16);
    }

    cudaFuncSetAttribute(f16_gemm_nt_bias,
                         cudaFuncAttributeMaxDynamicSharedMemorySize, GEMM_SMEM);

    // Fused QKV projection: N=6144, columns routed to Qlin/Klin/Vlin planes
    f16_gemm_nt_bias<<<dim3(3 * D_ / 256, M / 128), 512, GEMM_SMEM>>>(
        x16, w16, biasqkv, Qlin, M, K, NBSD);

    int rope_total = B_ * H_ * S_ * 64;
    rope_relayout_kernel<<<rope_total / 256, 256>>>(Qlin, Klin, Qh16, Kh16);
    v_pack_kernel<<<B_ * H_ * 4 * 32, 256>>>(Vlin, vp);

    cudaFuncSetAttribute(attn_mma_kernel,
                         cudaFuncAttributeMaxDynamicSharedMemorySize, ATT_SMEM);
    attn_mma_kernel<<<dim3(S_ / 128, H_, B_), 256, ATT_SMEM>>>(
        Qh16, Kh16, vp, O16);

    // Output projection (fp16 A from attention, fp32 C)
    f16_gemm_nt_bias<<<dim3(D_ / 256, M / 128), 512, GEMM_SMEM>>>(
        O16, Wot16, bo, out, M, K, 0);
}

// round 17
// speedup vs baseline: 1.0261x; 1.0261x over previous
#include <cuda_runtime.h>
#include <cuda_fp16.h>
#include <math.h>
#include <cstdint>
#include <cstring>

// Problem constants
#define B_ 2
#define S_ 2048
#define D_ 2048
#define H_ 16
#define DK_ 128

static const size_t NBSD = (size_t)B_ * S_ * D_;
// fp16 planes: Qpre, Kpre, Vpre (QKV GEMM out, head layout), Qh, Kh, O16
__device__ __half g_h16[6 * (size_t)B_ * S_ * D_];
// packed+transposed V: u32 half2(V[2s2][d],V[2s2+1][d]) at [b,h][d][s2]
__device__ uint32_t g_vp[(size_t)B_ * S_ * D_ / 2];
__device__ __half g_x16[(size_t)B_ * S_ * D_];        // fp16 x
__device__ __half g_w16[4 * (size_t)D_ * D_];         // fp16 Wq,Wk,Wv,Wo
__device__ float g_bias[3 * D_];                      // concat bq,bk,bv

// ============================================================================
// Helpers
// ============================================================================
__device__ __forceinline__ uint32_t smem_to_u32(const void* smem_ptr) {
    uint32_t addr;
    asm("{ .reg .u64 tmp; cvta.to.shared.u64 tmp, %1; cvt.u32.u64 %0, tmp; }"
        : "=r"(addr) : "l"(smem_ptr));
    return addr;
}

__device__ __forceinline__ uint32_t h2_as_u32(__half2 h) {
    uint32_t u;
    memcpy(&u, &h, 4);
    return u;
}

__device__ __forceinline__ void cp_async16(uint32_t smem_addr, const void* gptr) {
    asm volatile("cp.async.cg.shared.global [%0], [%1], 16;"
                 :: "r"(smem_addr), "l"(gptr));
}
#define CP_ASYNC_COMMIT() asm volatile("cp.async.commit_group;" ::: "memory")
#define CP_ASYNC_WAIT(n)  asm volatile("cp.async.wait_group %0;" :: "n"(n) : "memory")

__device__ __forceinline__ void ldsm_x4(uint32_t* r, uint32_t addr) {
    asm volatile("ldmatrix.sync.aligned.m8n8.x4.shared.b16 {%0,%1,%2,%3}, [%4];"
                 : "=r"(r[0]), "=r"(r[1]), "=r"(r[2]), "=r"(r[3]) : "r"(addr));
}

__device__ __forceinline__ void mma_f16_16n8k16(float* d, const uint32_t* a,
                                                const uint32_t* b) {
    asm volatile(
        "mma.sync.aligned.m16n8k16.row.col.f32.f16.f16.f32 "
        "{%0,%1,%2,%3}, {%4,%5,%6,%7}, {%8,%9}, {%0,%1,%2,%3};"
        : "+f"(d[0]), "+f"(d[1]), "+f"(d[2]), "+f"(d[3])
        : "r"(a[0]), "r"(a[1]), "r"(a[2]), "r"(a[3]), "r"(b[0]), "r"(b[1]));
}

// ============================================================================
// Pre-passes
// ============================================================================
__global__ __launch_bounds__(256) void f32_to_f16_kernel(
    const float* __restrict__ in, __half* __restrict__ out, int n4)
{
    int i = blockIdx.x * 256 + threadIdx.x;
    if (i >= n4) return;
    float4 v = ((const float4*)in)[i];
    uint2 w;
    w.x = h2_as_u32(__floats2half2_rn(v.x, v.y));
    w.y = h2_as_u32(__floats2half2_rn(v.z, v.w));
    ((uint2*)out)[i] = w;
}

__global__ __launch_bounds__(256) void w4_to_f16_kernel(
    const float* __restrict__ W0, const float* __restrict__ W1,
    const float* __restrict__ W2, const float* __restrict__ W3,
    __half* __restrict__ out)
{
    int i = blockIdx.x * 256 + threadIdx.x;     // 0 .. 4*2^20-1
    const int per = (D_ * D_) / 4;
    int p = i >> 20, j = i & (per - 1);
    const float* W = (p == 0) ? W0 : (p == 1) ? W1 : (p == 2) ? W2 : W3;
    float4 v = ((const float4*)W)[j];
    uint2 w;
    w.x = h2_as_u32(__floats2half2_rn(v.x, v.y));
    w.y = h2_as_u32(__floats2half2_rn(v.z, v.w));
    ((uint2*)out)[i] = w;
}

__global__ __launch_bounds__(256) void bias_gather_kernel(
    const float* __restrict__ bq, const float* __restrict__ bk,
    const float* __restrict__ bv, float* __restrict__ out)
{
    int i = blockIdx.x * 256 + threadIdx.x;     // 0..6143
    if (i >= 3 * D_) return;
    out[i] = (i < D_) ? bq[i] : (i < 2 * D_) ? bk[i - D_] : bv[i - 2 * D_];
}

// ============================================================================
// fp16 GEMM: acc(fp32) = A(fp16)[M,K] @ W(fp16)[N,K]^T + bias.
// BM=128, BN=256, BK=64, 256 threads = 8 warps (2 M x 4 N), warp tile 64x64.
// qkv_mode != 0: write fp16 HEAD-LAYOUT [B,H,S,DK] into 3 planes of stride
// qkv_mode (= NBSD). qkv_mode == 0: write fp32 row-major C (final output).
// ============================================================================
#define GA_BYTES (128 * 144)                     // A tile bytes
#define GEMM_STAGE_BYTES ((128 + 256) * 144)     // 55296
#define GEMM_SMEM (3 * GEMM_STAGE_BYTES + 16)

__device__ __forceinline__ void gemm16_load_stage(
    const __half* __restrict__ A, const __half* __restrict__ W,
    int row0, int col0, int K, int kc, uint32_t sbase, int tid)
{
#pragma unroll
    for (int i = 0; i < 4; i++) {
        int q = i * 256 + tid;           // 0..1023
        int r = q >> 3, c = q & 7;
        cp_async16(sbase + (uint32_t)(r * 144 + c * 16),
                   A + (size_t)(row0 + r) * K + kc * 64 + c * 8);
    }
#pragma unroll
    for (int i = 0; i < 8; i++) {
        int q = i * 256 + tid;           // 0..2047
        int r = q >> 3, c = q & 7;
        cp_async16(sbase + (uint32_t)GA_BYTES + (uint32_t)(r * 144 + c * 16),
                   W + (size_t)(col0 + r) * K + kc * 64 + c * 8);
    }
    CP_ASYNC_COMMIT();
}

__global__ __launch_bounds__(256) void f16_gemm_nt_bias(
    const __half* __restrict__ A, const __half* __restrict__ W,
    const float* __restrict__ bias, void* __restrict__ Cout,
    int M, int K, size_t qkv_mode)
{
    extern __shared__ __align__(16) char dsm[];

    int tid = threadIdx.x;
    int wid = tid >> 5;
    int lane = tid & 31;
    int gr = lane >> 2;
    int gc = lane & 3;
    int wm = wid & 1;
    int wn = wid >> 1;
    int lrow = lane & 7, lsel = lane >> 3;

    int bx = blockIdx.x, by = blockIdx.y;
    int row0 = by * 128, col0 = bx * 256;

    uint32_t sb = smem_to_u32(dsm);
    uint32_t afb = (uint32_t)((wm * 64 + (lsel & 1) * 8 + lrow) * 144 +
                              (lsel >> 1) * 16);
    uint32_t wfb = (uint32_t)GA_BYTES +
                   (uint32_t)((wn * 64 + (lsel >> 1) * 8 + lrow) * 144 +
                              (lsel & 1) * 16);

    float acc[4][8][4];
#pragma unroll
    for (int i = 0; i < 4; i++)
#pragma unroll
        for (int j = 0; j < 8; j++)
#pragma unroll
            for (int k = 0; k < 4; k++) acc[i][j][k] = 0.f;

    const int NC = K >> 6;   // 32

    gemm16_load_stage(A, W, row0, col0, K, 0, sb + 0 * GEMM_STAGE_BYTES, tid);
    gemm16_load_stage(A, W, row0, col0, K, 1, sb + 1 * GEMM_STAGE_BYTES, tid);

    for (int j = 0; j < NC; j++) {
        if (j + 2 < NC) { CP_ASYNC_WAIT(1); } else { CP_ASYNC_WAIT(0); }
        __syncthreads();

        int jn = j + 2;
        if (jn < NC) {
            gemm16_load_stage(A, W, row0, col0, K, jn,
                              sb + (jn % 3) * GEMM_STAGE_BYTES, tid);
        }

        uint32_t stage_b = sb + (uint32_t)((j % 3) * GEMM_STAGE_BYTES);

#pragma unroll
        for (int kst = 0; kst < 4; kst++) {
            uint32_t af[4][4];
#pragma unroll
            for (int ma = 0; ma < 4; ma++)
                ldsm_x4(af[ma], stage_b + afb +
                        (uint32_t)(ma * 16 * 144) + kst * 32);
            uint32_t wf[4][4];
#pragma unroll
            for (int np = 0; np < 4; np++)
                ldsm_x4(wf[np], stage_b + wfb +
                        (uint32_t)(np * 16 * 144) + kst * 32);
#pragma unroll
            for (int ma = 0; ma < 4; ma++)
#pragma unroll
                for (int np = 0; np < 4; np++) {
                    mma_f16_16n8k16(acc[ma][2 * np], af[ma], &wf[np][0]);
                    mma_f16_16n8k16(acc[ma][2 * np + 1], af[ma], &wf[np][2]);
                }
        }
        __syncthreads();
    }

    if (qkv_mode) {
        // fp16 head-layout: plane p = col>>11, h = (col&2047)>>7, i = col&127
        __half* Ch = (__half*)Cout;
#pragma unroll
        for (int ma = 0; ma < 4; ma++) {
            int row = row0 + wm * 64 + ma * 16 + gr;
            int b = row >> 11, s = row & 2047;
#pragma unroll
            for (int na = 0; na < 8; na++) {
                int cf = col0 + wn * 64 + na * 8 + gc * 2;
                float2 bb = *(const float2*)(bias + cf);
                int p = cf >> 11, cp = cf & 2047;
                int h = cp >> 7, ii = cp & 127;
                __half* dst = Ch + (size_t)p * qkv_mode +
                              ((size_t)((b * H_ + h) * S_ + s)) * DK_ + ii;
                *(uint32_t*)dst = h2_as_u32(__floats2half2_rn(
                    acc[ma][na][0] + bb.x, acc[ma][na][1] + bb.y));
                *(uint32_t*)(dst + 8 * DK_) = h2_as_u32(__floats2half2_rn(
                    acc[ma][na][2] + bb.x, acc[ma][na][3] + bb.y));
            }
        }
    } else {
        float* C = (float*)Cout;
#pragma unroll
        for (int ma = 0; ma < 4; ma++) {
            int row = row0 + wm * 64 + ma * 16 + gr;
#pragma unroll
            for (int na = 0; na < 8; na++) {
                int cf = col0 + wn * 64 + na * 8 + gc * 2;
                float2 bb = *(const float2*)(bias + cf);
                float2 o0, o1;
                o0.x = acc[ma][na][0] + bb.x;
                o0.y = acc[ma][na][1] + bb.y;
                o1.x = acc[ma][na][2] + bb.x;
                o1.y = acc[ma][na][3] + bb.y;
                *(float2*)(C + (size_t)row * D_ + cf) = o0;
                *(float2*)(C + (size_t)(row + 8) * D_ + cf) = o1;
            }
        }
    }
}

// ---------------------------------------------------------------------------
// RoPE (fp16 in, fp16 out, head layout both sides).
// ---------------------------------------------------------------------------
__global__ __launch_bounds__(256) void rope_kernel(
    const __half* __restrict__ Qpre, const __half* __restrict__ Kpre,
    __half* __restrict__ Qh, __half* __restrict__ Kh)
{
    int idx = blockIdx.x * 256 + threadIdx.x;          // B*H*S*64
    if (idx >= B_ * H_ * S_ * 64) return;
    int i  = idx & 63;
    int s  = (idx >> 6) & (S_ - 1);
    int hb = idx >> 17;

    size_t out = ((size_t)hb * S_ + s) * DK_ + i;

    // inv = 10000^(-i/64) = exp(-i * ln(10000)/64)
    float inv = __expf(-(float)i * 0.14391156831212787f);
    float ang = (float)s * inv;
    float sn, cs;
    sincosf(ang, &sn, &cs);

    float q0 = __half2float(Qpre[out]), q1 = __half2float(Qpre[out + 64]);
    Qh[out]      = __float2half_rn(q0 * cs - q1 * sn);
    Qh[out + 64] = __float2half_rn(q1 * cs + q0 * sn);

    float k0 = __half2float(Kpre[out]), k1 = __half2float(Kpre[out + 64]);
    Kh[out]      = __float2half_rn(k0 * cs - k1 * sn);
    Kh[out + 64] = __float2half_rn(k1 * cs + k0 * sn);
}

// ---------------------------------------------------------------------------
// V pack + transpose: head-layout fp16 -> Vt[b,h][d][s2] u32 half2 pairs.
// ---------------------------------------------------------------------------
__global__ __launch_bounds__(256) void v_pack_kernel(
    const __half* __restrict__ Vpre, uint32_t* __restrict__ Vp)
{
    __shared__ uint32_t tile[32][33];
    int blk = blockIdx.x;                // B*H * 4 * 32 = 4096
    int s2b = (blk & 31) * 32;
    int db  = ((blk >> 5) & 3) * 32;
    int hb  = blk >> 7;
    int t = threadIdx.x;

#pragma unroll
    for (int it = 0; it < 4; it++) {
        int idx = it * 256 + t;
        int s2l = idx >> 5, dl = idx & 31;
        const __half* src = Vpre + (size_t)hb * S_ * DK_ +
                            (size_t)(2 * (s2b + s2l)) * DK_ + db + dl;
        tile[s2l][dl] = h2_as_u32(__halves2half2(src[0], src[DK_]));
    }
    __syncthreads();
#pragma unroll
    for (int it = 0; it < 4; it++) {
        int idx = it * 256 + t;
        int dl = idx >> 5, s2l = idx & 31;
        Vp[((size_t)hb * DK_ + db + dl) * (S_ / 2) + s2b + s2l] = tile[s2l][dl];
    }
}

// ---------------------------------------------------------------------------
// Tensor-core flash attention (causal), FA2 + LDSM, single-pass fp16 scores.
// BM=128, BN=64, 8 warps; warp owns 16 q-rows. One barrier per kv-group.
// ---------------------------------------------------------------------------
#define AHSTR 136                        // fp16 K/Q row stride (halves)
#define VTSTR 36                         // Vt row stride (u32)
#define VT_OFF (4352 * 4)                // bytes: Vt tile within stage
#define STG_F 8960                       // stage floats: KH 4352 + VT 4608
#define ATT_FLOATS (3 * STG_F)           // 26880
#define ATT_SMEM (ATT_FLOATS * 4)        // 107520 bytes

__global__ __launch_bounds__(256, 1) void attn_mma_kernel(
    const __half* __restrict__ Qh_g, const __half* __restrict__ Kh_g,
    const uint32_t* __restrict__ Vp_g, __half* __restrict__ O16)
{
    extern __shared__ __align__(16) float sm[];
    uint32_t sb = smem_to_u32(sm);

    int qt = (int)gridDim.x - 1 - (int)blockIdx.x;
    int h = blockIdx.y, b = blockIdx.z;
    int hb = b * H_ + h;
    size_t base = (size_t)hb * S_ * DK_;
    size_t qoff = base + (size_t)qt * 128 * DK_;
    size_t vbase = (size_t)hb * DK_ * (S_ / 2);

    int tid = threadIdx.x;
    int wid = tid >> 5;
    int lane = tid & 31;
    int gr = lane >> 2, gc = lane & 3;

    int r0 = wid * 16 + gr;
    int rbase = qt * 128;

#pragma unroll
    for (int i = 0; i < 8; i++) {
        int q = i * 256 + tid;
        int r = q >> 4, c = q & 15;
        cp_async16(sb + (uint32_t)(r * AHSTR * 2 + c * 16),
                   Qh_g + qoff + (size_t)r * DK_ + c * 8);
    }
    CP_ASYNC_COMMIT();
    CP_ASYNC_WAIT(0);
    __syncthreads();

    uint32_t qh[8][4];
    {
        const __half* Qhp = (const __half*)sm;
#pragma unroll
        for (int kst = 0; kst < 8; kst++) {
            int k0 = kst * 16;
            qh[kst][0] = *(const uint32_t*)&Qhp[r0 * AHSTR + k0 + 2 * gc];
            qh[kst][1] = *(const uint32_t*)&Qhp[(r0 + 8) * AHSTR + k0 + 2 * gc];
            qh[kst][2] = *(const uint32_t*)&Qhp[r0 * AHSTR + k0 + 2 * gc + 8];
            qh[kst][3] = *(const uint32_t*)&Qhp[(r0 + 8) * AHSTR + k0 + 2 * gc + 8];
        }
    }
    __syncthreads();   // stage-0 area free for K/V ring

    int lrow = lane & 7, lsel = lane >> 3;
    uint32_t kfb = (uint32_t)(((lsel >> 1) * 8 + lrow) * (AHSTR * 2) +
                              (lsel & 1) * 16);
    uint32_t vfb = (uint32_t)VT_OFF +
                   (uint32_t)(((lsel >> 1) * 8 + lrow) * (VTSTR * 4)) +
                   (uint32_t)(lsel & 1) * 16u;

    int nkt = 2 * qt + 2;

    auto load_group = [&](int j, int s) {
        size_t kb = base + (size_t)j * 64 * DK_;
        size_t vt = vbase + (size_t)j * 32;
        uint32_t st = sb + (uint32_t)(s * STG_F) * 4;
#pragma unroll
        for (int i = 0; i < 4; i++) {
            int q = i * 256 + tid;   // 0..1023 (64 rows x 16 chunks)
            int r = q >> 4, c = q & 15;
            cp_async16(st + (uint32_t)(r * AHSTR * 2 + c * 16),
                       Kh_g + kb + (size_t)r * DK_ + c * 8);
        }
#pragma unroll
        for (int i = 0; i < 4; i++) {
            int q = i * 256 + tid;   // 0..1023 (128 d-rows x 8 chunks)
            int r = q >> 3, c = q & 7;
            cp_async16(st + VT_OFF + (uint32_t)(r * VTSTR * 4 + c * 16),
                       Vp_g + vt + (size_t)r * (S_ / 2) + c * 4);
        }
        CP_ASYNC_COMMIT();
    };

    load_group(0, 0);
    if (nkt > 1) load_group(1, 1);

    float oacc[16][4];
#pragma unroll
    for (int i = 0; i < 16; i++)
#pragma unroll
        for (int j = 0; j < 4; j++) oacc[i][j] = 0.f;

    float m0 = -1e30f, m1 = -1e30f, l0 = 0.f, l1 = 0.f;
    const float scale = 0.088388347648318440f;

    for (int j = 0; j < nkt; j++) {
        if (j + 1 < nkt) { CP_ASYNC_WAIT(1); } else { CP_ASYNC_WAIT(0); }
        __syncthreads();

        if (j + 2 < nkt) load_group(j + 2, (j + 2) % 3);

        uint32_t stage_b = sb + (uint32_t)((j % 3) * STG_F) * 4;

        float sacc[8][4];
#pragma unroll
        for (int i = 0; i < 8; i++)
#pragma unroll
            for (int k = 0; k < 4; k++) sacc[i][k] = 0.f;

#pragma unroll
        for (int kst = 0; kst < 8; kst++) {
#pragma unroll
            for (int np = 0; np < 4; np++) {
                uint32_t kf[4];
                ldsm_x4(kf, stage_b + kfb +
                        (uint32_t)(np * 16 * AHSTR * 2) + kst * 32);
                mma_f16_16n8k16(sacc[2 * np], qh[kst], &kf[0]);
                mma_f16_16n8k16(sacc[2 * np + 1], qh[kst], &kf[2]);
            }
        }

        bool diag = (j >= 2 * qt);
        int rg0 = rbase + r0, rg1 = rg0 + 8;
#pragma unroll
        for (int na = 0; na < 8; na++) {
            float s0 = sacc[na][0] * scale;
            float s1 = sacc[na][1] * scale;
            float s2 = sacc[na][2] * scale;
            float s3 = sacc[na][3] * scale;
            if (diag) {
                int cg = j * 64 + na * 8 + 2 * gc;
                if (cg > rg0) s0 = -1e30f;
                if (cg + 1 > rg0) s1 = -1e30f;
                if (cg > rg1) s2 = -1e30f;
                if (cg + 1 > rg1) s3 = -1e30f;
            }
            sacc[na][0] = s0; sacc[na][1] = s1;
            sacc[na][2] = s2; sacc[na][3] = s3;
        }

        float rm0 = -1e30f, rm1 = -1e30f;
#pragma unroll
        for (int na = 0; na < 8; na++) {
            rm0 = fmaxf(rm0, fmaxf(sacc[na][0], sacc[na][1]));
            rm1 = fmaxf(rm1, fmaxf(sacc[na][2], sacc[na][3]));
        }
        rm0 = fmaxf(rm0, __shfl_xor_sync(0xffffffffu, rm0, 1));
        rm0 = fmaxf(rm0, __shfl_xor_sync(0xffffffffu, rm0, 2));
        rm1 = fmaxf(rm1, __shfl_xor_sync(0xffffffffu, rm1, 1));
        rm1 = fmaxf(rm1, __shfl_xor_sync(0xffffffffu, rm1, 2));

        float mn0 = fmaxf(m0, rm0), mn1 = fmaxf(m1, rm1);
        float a0 = __expf(m0 - mn0), a1 = __expf(m1 - mn1);
        m0 = mn0; m1 = mn1;

        uint32_t ap[4][4];
        float sum0 = 0.f, sum1 = 0.f;
#pragma unroll
        for (int kst = 0; kst < 4; kst++) {
            int e = 2 * kst, o = 2 * kst + 1;
            __half2 h00 = __floats2half2_rn(__expf(sacc[e][0] - mn0),
                                            __expf(sacc[e][1] - mn0));
            __half2 h01 = __floats2half2_rn(__expf(sacc[e][2] - mn1),
                                            __expf(sacc[e][3] - mn1));
            __half2 h10 = __floats2half2_rn(__expf(sacc[o][0] - mn0),
                                            __expf(sacc[o][1] - mn0));
            __half2 h11 = __floats2half2_rn(__expf(sacc[o][2] - mn1),
                                            __expf(sacc[o][3] - mn1));
            ap[kst][0] = h2_as_u32(h00);
            ap[kst][1] = h2_as_u32(h01);
            ap[kst][2] = h2_as_u32(h10);
            ap[kst][3] = h2_as_u32(h11);
            float2 f;
            f = __half22float2(h00); sum0 += f.x + f.y;
            f = __half22float2(h10); sum0 += f.x + f.y;
            f = __half22float2(h01); sum1 += f.x + f.y;
            f = __half22float2(h11); sum1 += f.x + f.y;
        }
        sum0 += __shfl_xor_sync(0xffffffffu, sum0, 1);
        sum0 += __shfl_xor_sync(0xffffffffu, sum0, 2);
        sum1 += __shfl_xor_sync(0xffffffffu, sum1, 1);
        sum1 += __shfl_xor_sync(0xffffffffu, sum1, 2);
        l0 = l0 * a0 + sum0;
        l1 = l1 * a1 + sum1;

#pragma unroll
        for (int na = 0; na < 16; na++) {
            oacc[na][0] *= a0; oacc[na][1] *= a0;
            oacc[na][2] *= a1; oacc[na][3] *= a1;
        }

#pragma unroll
        for (int kst = 0; kst < 4; kst++) {
#pragma unroll
            for (int np = 0; np < 8; np++) {
                uint32_t vf[4];
                ldsm_x4(vf, stage_b + vfb +
                        (uint32_t)(np * 16 * VTSTR * 4) + kst * 32);
                mma_f16_16n8k16(oacc[2 * np], ap[kst], vf);
                mma_f16_16n8k16(oacc[2 * np + 1], ap[kst], vf + 2);
            }
        }
    }

    float li0 = 1.0f / l0;
    float li1 = 1.0f / l1;
    int srow0 = rbase + r0;
    __half* Og0 = O16 + ((size_t)b * S_ + srow0) * D_ + h * DK_;
    __half* Og1 = O16 + ((size_t)b * S_ + srow0 + 8) * D_ + h * DK_;
#pragma unroll
    for (int na = 0; na < 16; na++) {
        int col = na * 8 + 2 * gc;
        *(uint32_t*)(Og0 + col) =
            h2_as_u32(__floats2half2_rn(oacc[na][0] * li0, oacc[na][1] * li0));
        *(uint32_t*)(Og1 + col) =
            h2_as_u32(__floats2half2_rn(oacc[na][2] * li1, oacc[na][3] * li1));
    }
}

// ---------------------------------------------------------------------------
extern "C" void kernel_launch(void* const* d_in, const int* in_sizes, int n_in,
                              void* d_out, int out_size)
{
    const float* x  = (const float*)d_in[0];
    const float* Wq = (const float*)d_in[2];
    const float* bq = (const float*)d_in[3];
    const float* Wk = (const float*)d_in[4];
    const float* bk = (const float*)d_in[5];
    const float* Wv = (const float*)d_in[6];
    const float* bv = (const float*)d_in[7];
    const float* Wo = (const float*)d_in[8];
    const float* bo = (const float*)d_in[9];
    float* out = (float*)d_out;

    __half* hbase = nullptr;
    cudaGetSymbolAddress((void**)&hbase, g_h16);
    uint32_t* vp = nullptr;
    cudaGetSymbolAddress((void**)&vp, g_vp);
    __half* x16 = nullptr;
    cudaGetSymbolAddress((void**)&x16, g_x16);
    __half* w16 = nullptr;
    cudaGetSymbolAddress((void**)&w16, g_w16);
    float* biasqkv = nullptr;
    cudaGetSymbolAddress((void**)&biasqkv, g_bias);

    __half* Qpre = hbase;                // plane 0 (QKV GEMM out, head layout)
    __half* Kpre = hbase + NBSD;         // plane 1
    __half* Vpre = hbase + 2 * NBSD;     // plane 2
    __half* Qh16 = hbase + 3 * NBSD;
    __half* Kh16 = hbase + 4 * NBSD;
    __half* O16  = hbase + 5 * NBSD;
    __half* Wot16 = w16 + 3 * (size_t)D_ * D_;

    const int M = B_ * S_, K = D_;

    bias_gather_kernel<<<(3 * D_ + 255) / 256, 256>>>(bq, bk, bv, biasqkv);
    {
        int nx4 = (int)(NBSD / 4);
        f32_to_f16_kernel<<<(nx4 + 255) / 256, 256>>>(x, x16, nx4);
        w4_to_f16_kernel<<<16384, 256>>>(Wq, Wk, Wv, Wo, w16);
    }

    cudaFuncSetAttribute(f16_gemm_nt_bias,
                         cudaFuncAttributeMaxDynamicSharedMemorySize, GEMM_SMEM);

    // Fused QKV projection: fp16 head-layout output into Qpre/Kpre/Vpre
    f16_gemm_nt_bias<<<dim3(3 * D_ / 256, M / 128), 256, GEMM_SMEM>>>(
        x16, w16, biasqkv, Qpre, M, K, NBSD);

    int rope_total = B_ * H_ * S_ * 64;
    rope_kernel<<<rope_total / 256, 256>>>(Qpre, Kpre, Qh16, Kh16);
    v_pack_kernel<<<B_ * H_ * 4 * 32, 256>>>(Vpre, vp);

    cudaFuncSetAttribute(attn_mma_kernel,
                         cudaFuncAttributeMaxDynamicSharedMemorySize, ATT_SMEM);
    attn_mma_kernel<<<dim3(S_ / 128, H_, B_), 256, ATT_SMEM>>>(
        Qh16, Kh16, vp, O16);

    // Output projection (fp32 out + bias)
    f16_gemm_nt_bias<<<dim3(D_ / 256, M / 128), 256, GEMM_SMEM>>>(
        O16, Wot16, bo, out, M, K, 0);
}